// round 14
// baseline (speedup 1.0000x reference)
#include <cuda_runtime.h>
#include <cstdint>
#include <math.h>

// Problem constants
#define EDIM 512
#define NSEQ 4096
#define NHEAD 8
#define HDIM 2048

typedef unsigned long long u64;

// ---- tf32 mma.sync helpers (family-agnostic PTX, works on compute_103) ----
__device__ __forceinline__ uint32_t tf32r(float f) {
    uint32_t u;
    asm("cvt.rna.tf32.f32 %0, %1;" : "=r"(u) : "f"(f));
    return u;
}
__device__ __forceinline__ float tf32rf(float f) {
    return __uint_as_float(tf32r(f));
}
__device__ __forceinline__ void mma1688(float* c, const uint32_t* a, const uint32_t* b) {
    asm volatile(
        "mma.sync.aligned.m16n8k8.row.col.f32.tf32.tf32.f32 "
        "{%0,%1,%2,%3}, {%4,%5,%6,%7}, {%8,%9}, {%0,%1,%2,%3};"
        : "+f"(c[0]), "+f"(c[1]), "+f"(c[2]), "+f"(c[3])
        : "r"(a[0]), "r"(a[1]), "r"(a[2]), "r"(a[3]), "r"(b[0]), "r"(b[1]));
}
__device__ __forceinline__ void ldsm_x4(uint32_t* r, uint32_t saddr) {
    asm volatile("ldmatrix.sync.aligned.m8n8.x4.shared.b16 {%0,%1,%2,%3}, [%4];"
                 : "=r"(r[0]), "=r"(r[1]), "=r"(r[2]), "=r"(r[3]) : "r"(saddr));
}
__device__ __forceinline__ uint32_t smem_u32(const void* p) {
    uint32_t a;
    asm("{ .reg .u64 t; cvta.to.shared.u64 t, %1; cvt.u32.u64 %0, t; }" : "=r"(a) : "l"(p));
    return a;
}
__device__ __forceinline__ void cpa16(uint32_t s, const void* g) {
    asm volatile("cp.async.cg.shared.global [%0], [%1], 16;" :: "r"(s), "l"(g));
}
#define CP_COMMIT() asm volatile("cp.async.commit_group;" ::: "memory")
#define CP_WAIT0()  asm volatile("cp.async.wait_group 0;" ::: "memory")
#define CP_WAIT1()  asm volatile("cp.async.wait_group 1;" ::: "memory")

// Scratch (alloc-free rule: __device__ globals)
__device__ float g_h1[NSEQ * EDIM];
__device__ float g_qkv[NSEQ * 3 * EDIM];
__device__ float g_attn[NSEQ * EDIM];
__device__ float g_x1[NSEQ * EDIM];
__device__ float g_h2[NSEQ * EDIM];
__device__ float g_m1[NSEQ * HDIM];
__device__ float g_m2[NSEQ * HDIM];
// tf32-pre-rounded weights
__device__ float g_wqkv[3 * EDIM * EDIM];
__device__ float g_wproj[EDIM * EDIM];
__device__ float g_w1[HDIM * EDIM];
__device__ float g_w2[HDIM * HDIM];
__device__ float g_w3[EDIM * HDIM];

// ===========================================================================
// Weight pre-rounding, single fused kernel over 5 segments (float4 units)
// ===========================================================================
__global__ void round_w_all(const float* __restrict__ s0, float* __restrict__ d0,
                            const float* __restrict__ s1, float* __restrict__ d1,
                            const float* __restrict__ s2, float* __restrict__ d2,
                            const float* __restrict__ s3, float* __restrict__ d3,
                            const float* __restrict__ s4, float* __restrict__ d4) {
    int i = blockIdx.x * blockDim.x + threadIdx.x;
    const float* s; float* d; int off;
    if (i < 196608)       { s = s0; d = d0; off = i; }
    else if (i < 262144)  { s = s1; d = d1; off = i - 196608; }
    else if (i < 524288)  { s = s2; d = d2; off = i - 262144; }
    else if (i < 1572864) { s = s3; d = d3; off = i - 524288; }
    else                  { s = s4; d = d4; off = i - 1572864; }
    float4 v = ((const float4*)s)[off];
    v.x = tf32rf(v.x); v.y = tf32rf(v.y); v.z = tf32rf(v.z); v.w = tf32rf(v.w);
    ((float4*)d)[off] = v;
}

// ===========================================================================
// LayerNorm (output rounded to tf32-exact fp32)
// ===========================================================================
__global__ void ln_kernel(const float* __restrict__ X, const float* __restrict__ g,
                          const float* __restrict__ b, float* __restrict__ Y) {
    const int row = blockIdx.x;
    const int t = threadIdx.x;  // 128 threads
    const float4* Xv = (const float4*)(X + (size_t)row * EDIM);
    float4 v = Xv[t];

    __shared__ float red[4];
    float s = v.x + v.y + v.z + v.w;
    #pragma unroll
    for (int o = 16; o > 0; o >>= 1) s += __shfl_down_sync(0xffffffffu, s, o);
    if ((t & 31) == 0) red[t >> 5] = s;
    __syncthreads();
    float mean = (red[0] + red[1] + red[2] + red[3]) * (1.0f / EDIM);
    __syncthreads();

    float dx = v.x - mean, dy = v.y - mean, dz = v.z - mean, dw = v.w - mean;
    float s2 = dx * dx + dy * dy + dz * dz + dw * dw;
    #pragma unroll
    for (int o = 16; o > 0; o >>= 1) s2 += __shfl_down_sync(0xffffffffu, s2, o);
    if ((t & 31) == 0) red[t >> 5] = s2;
    __syncthreads();
    float var = (red[0] + red[1] + red[2] + red[3]) * (1.0f / EDIM);
    float rs = rsqrtf(var + 1e-5f);

    float4 gv = ((const float4*)g)[t];
    float4 bv = ((const float4*)b)[t];
    float4 o4;
    o4.x = tf32rf(dx * rs * gv.x + bv.x);
    o4.y = tf32rf(dy * rs * gv.y + bv.y);
    o4.z = tf32rf(dz * rs * gv.z + bv.z);
    o4.w = tf32rf(dw * rs * gv.w + bv.w);
    ((float4*)(Y + (size_t)row * EDIM))[t] = o4;
}

// ===========================================================================
// tf32 mma.sync GEMM (unchanged, passing)
// ===========================================================================
#define SMS 20

template <int MT, bool RELU, bool RES, bool ROUND>
__global__ void __launch_bounds__(256, 2)
mma_gemm(const float* __restrict__ A, const float* __restrict__ B,
         const float* __restrict__ bias, const float* __restrict__ Rs,
         float* __restrict__ C, int M, int N, int K) {
    constexpr int A_STAGE = MT * SMS;
    constexpr int B_STAGE = 128 * SMS;
    constexpr int MI = MT / 32;
    constexpr int LA = MT / 64;

    extern __shared__ uint32_t dsm[];
    uint32_t* sA = dsm;
    uint32_t* sB = dsm + 3 * A_STAGE;

    const int t = threadIdx.x;
    const int wid = t >> 5;
    const int lid = t & 31;
    const int mBase = blockIdx.y * MT;
    const int nBase = blockIdx.x * 128;

    const int wm = (wid >> 2) * (MT / 2);
    const int wn = (wid & 3) * 32;
    const int g = lid >> 2;
    const int t4 = lid & 3;

    float acc[MI][4][4];
    #pragma unroll
    for (int mi = 0; mi < MI; mi++)
        #pragma unroll
        for (int ni = 0; ni < 4; ni++)
            #pragma unroll
            for (int r = 0; r < 4; r++) acc[mi][ni][r] = 0.0f;

    const float* ApL[LA];
    uint32_t saL[3][LA];
    #pragma unroll
    for (int i = 0; i < LA; i++) {
        int s = t * LA + i;
        int row = s >> 2, q = (s & 3) * 4;
        ApL[i] = A + (size_t)(mBase + row) * K + q;
        #pragma unroll
        for (int st = 0; st < 3; st++)
            saL[st][i] = smem_u32(&sA[st * A_STAGE + row * SMS + q]);
    }
    const float* BpL[2];
    uint32_t sbL[3][2];
    #pragma unroll
    for (int i = 0; i < 2; i++) {
        int s = t * 2 + i;
        int row = s >> 2, q = (s & 3) * 4;
        BpL[i] = B + (size_t)(nBase + row) * K + q;
        #pragma unroll
        for (int st = 0; st < 3; st++)
            sbL[st][i] = smem_u32(&sB[st * B_STAGE + row * SMS + q]);
    }

    const int a_elem = (wm + (lid & 15)) * SMS + ((lid >> 4) << 2);
    const int b_elem = (wn + ((lid >> 4) << 3) + (lid & 7)) * SMS + (((lid >> 3) & 1) << 2);
    uint32_t aB[3], bB[3];
    #pragma unroll
    for (int st = 0; st < 3; st++) {
        aB[st] = smem_u32(&sA[st * A_STAGE + a_elem]);
        bB[st] = smem_u32(&sB[st * B_STAGE + b_elem]);
    }

    auto issue_chunk = [&](int c, int st) {
        const int k0 = c << 4;
        #pragma unroll
        for (int i = 0; i < LA; i++) cpa16(saL[st][i], ApL[i] + k0);
        #pragma unroll
        for (int i = 0; i < 2; i++) cpa16(sbL[st][i], BpL[i] + k0);
    };

    const int T = K >> 4;
    issue_chunk(0, 0); CP_COMMIT();
    if (T > 1) { issue_chunk(1, 1); CP_COMMIT(); }

    int st = 0;
    for (int c = 0; c < T; c++) {
        if (c + 1 < T) CP_WAIT1(); else CP_WAIT0();
        __syncthreads();
        if (c + 2 < T) { issue_chunk(c + 2, (st + 2 >= 3) ? st - 1 : st + 2); CP_COMMIT(); }

        const uint32_t aBs = aB[st];
        const uint32_t bBs = bB[st];
        #pragma unroll
        for (int ks = 0; ks < 16; ks += 8) {
            uint32_t af[MI][4], bfr[2][4];
            #pragma unroll
            for (int mi = 0; mi < MI; mi++)
                ldsm_x4(af[mi], aBs + (mi * 16 * SMS + ks) * 4);
            #pragma unroll
            for (int nb = 0; nb < 2; nb++)
                ldsm_x4(bfr[nb], bBs + (nb * 16 * SMS + ks) * 4);
            #pragma unroll
            for (int mi = 0; mi < MI; mi++)
                #pragma unroll
                for (int ni = 0; ni < 4; ni++)
                    mma1688(acc[mi][ni], af[mi], &bfr[ni >> 1][(ni & 1) * 2]);
        }
        st = (st + 1 == 3) ? 0 : st + 1;
    }

    #pragma unroll
    for (int mi = 0; mi < MI; mi++) {
        #pragma unroll
        for (int ni = 0; ni < 4; ni++) {
            const int cc = nBase + wn + ni * 8 + 2 * t4;
            const float b0 = bias[cc], b1 = bias[cc + 1];
            #pragma unroll
            for (int h = 0; h < 2; h++) {
                const int row = mBase + wm + mi * 16 + g + h * 8;
                float v0 = acc[mi][ni][2 * h + 0] + b0;
                float v1 = acc[mi][ni][2 * h + 1] + b1;
                if (RES) {
                    const float* rr = Rs + (size_t)row * N + cc;
                    v0 += rr[0]; v1 += rr[1];
                }
                if (RELU) { v0 = fmaxf(v0, 0.0f); v1 = fmaxf(v1, 0.0f); }
                if (ROUND) { v0 = tf32rf(v0); v1 = tf32rf(v1); }
                float2 o; o.x = v0; o.y = v1;
                *(float2*)(C + (size_t)row * N + cc) = o;
            }
        }
    }
}

static int gemm_smem(int mt) { return 3 * (mt + 128) * SMS * 4; }

// ===========================================================================
// Tensor-core flash attention v2 (R13 structure, FIXED K/V loader):
// 256 threads (8 warps, 16 q-rows/warp), cp.async double-buffered K/V,
// softmax split 2 threads/row.
// K/V tile = 2048 16B slots: s in [0,2048), mat=s>>10, r=(s&1023)>>4, q=s&15.
// 8 slots/thread, s = t + 256*i (coalesced: 16 consecutive slots = 1 row).
// ===========================================================================
#define AQ_S 68
#define AV_S 72
#define K_STG (64 * AQ_S)   // uint32 per K buffer
#define V_STG (64 * AV_S)   // uint32 per V buffer

__global__ void __launch_bounds__(256)
attn_mma_kernel(const float* __restrict__ qkv, float* __restrict__ out) {
    extern __shared__ uint32_t asmem[];
    uint32_t* Qs = asmem;                       // 128 x 68
    uint32_t* Ks = Qs + 128 * AQ_S;             // 2 x 64 x 68
    uint32_t* Vs = Ks + 2 * K_STG;              // 2 x 64 x 72
    uint32_t* Ss = Vs + 2 * V_STG;              // 128 x 68
    float* rowM = (float*)(Ss + 128 * AQ_S);    // 128
    float* rowL = rowM + 128;                   // 128
    float* rowA = rowL + 128;                   // 128

    const int t = threadIdx.x;      // 256
    const int wid = t >> 5;
    const int lid = t & 31;
    const int g = lid >> 2, t4 = lid & 3;
    const int h = blockIdx.y;
    const int qb = blockIdx.x * 128;
    const int wrow = wid * 16;

    // Load Q tile once (scale by 2^-3 is exact; qkv already tf32-exact)
    for (int i = t; i < 128 * 16; i += 256) {
        int r = i >> 4, d4 = (i & 15) * 4;
        float4 q = *(const float4*)(qkv + (size_t)(qb + r) * 1536 + h * 64 + d4);
        q.x *= 0.125f; q.y *= 0.125f; q.z *= 0.125f; q.w *= 0.125f;
        *(float4*)&((float*)Qs)[r * AQ_S + d4] = q;
    }
    if (t < 128) { rowM[t] = -1e30f; rowL[t] = 0.0f; }

    // cp.async K/V loader: 2048 16B slots per tile, 8 per thread
    const float* gsrc[8];
    uint32_t dst0[8];      // smem addr in buffer 0
    uint32_t dstep[8];     // byte offset from buffer 0 to buffer 1
    #pragma unroll
    for (int i = 0; i < 8; i++) {
        int s = t + 256 * i;
        int mat = s >> 10;              // 0 = K, 1 = V
        int rem = s & 1023;
        int r = rem >> 4;               // key row 0..63
        int q = rem & 15;               // 16B quad 0..15
        gsrc[i] = qkv + (size_t)r * 1536 + h * 64 + 512 + mat * 512 + q * 4;
        if (mat == 0) {
            dst0[i] = smem_u32(&Ks[r * AQ_S + q * 4]);
            dstep[i] = K_STG * 4;
        } else {
            dst0[i] = smem_u32(&Vs[r * AV_S + q * 4]);
            dstep[i] = V_STG * 4;
        }
    }
    auto issue_tile = [&](int kb, int buf) {
        #pragma unroll
        for (int i = 0; i < 8; i++)
            cpa16(dst0[i] + buf * dstep[i], gsrc[i] + (size_t)kb * 1536);
    };

    float o[8][4];
    #pragma unroll
    for (int ni = 0; ni < 8; ni++)
        #pragma unroll
        for (int r = 0; r < 4; r++) o[ni][r] = 0.0f;

    const int NT = NSEQ / 64;
    issue_tile(0, 0); CP_COMMIT();

    for (int c = 0; c < NT; c++) {
        const int buf = c & 1;
        CP_WAIT0();
        __syncthreads();  // K/V tile c visible; prev iter compute done
        if (c + 1 < NT) { issue_tile((c + 1) * 64, buf ^ 1); CP_COMMIT(); }

        const uint32_t* Kb = Ks + buf * K_STG;
        const uint32_t* Vb = Vs + buf * V_STG;

        // S = Q*K^T: warp rows [wrow, wrow+16), cols 0..63
        float sf[8][4];
        #pragma unroll
        for (int ni = 0; ni < 8; ni++)
            #pragma unroll
            for (int r = 0; r < 4; r++) sf[ni][r] = 0.0f;

        #pragma unroll
        for (int ks = 0; ks < 64; ks += 8) {
            uint32_t af[4];
            int base = (wrow + g) * AQ_S + ks + t4;
            af[0] = Qs[base];
            af[1] = Qs[base + 8 * AQ_S];
            af[2] = Qs[base + 4];
            af[3] = Qs[base + 8 * AQ_S + 4];
            #pragma unroll
            for (int ni = 0; ni < 8; ni++) {
                uint32_t bf[2];
                int bb = (ni * 8 + g) * AQ_S + ks + t4;
                bf[0] = Kb[bb];
                bf[1] = Kb[bb + 4];
                mma1688(sf[ni], af, bf);
            }
        }
        // Write S fragments
        {
            int r0 = wrow + g;
            #pragma unroll
            for (int ni = 0; ni < 8; ni++) {
                int cc = ni * 8 + 2 * t4;
                float2 lo; lo.x = sf[ni][0]; lo.y = sf[ni][1];
                float2 hi; hi.x = sf[ni][2]; hi.y = sf[ni][3];
                *(float2*)&((float*)Ss)[r0 * AQ_S + cc] = lo;
                *(float2*)&((float*)Ss)[(r0 + 8) * AQ_S + cc] = hi;
            }
        }
        __syncthreads();

        // Softmax: 2 threads per row (cols 0-31 / 32-63), shfl combine
        {
            const int r = t >> 1;
            const int half = (t & 1) * 32;
            float* Sr = (float*)Ss + r * AQ_S + half;
            uint32_t* Pr = Ss + r * AQ_S + half;
            float mprev = rowM[r];
            float mx = mprev;
            #pragma unroll 8
            for (int j = 0; j < 32; j++) mx = fmaxf(mx, Sr[j]);
            mx = fmaxf(mx, __shfl_xor_sync(0xffffffffu, mx, 1));
            float sum = 0.0f;
            #pragma unroll 8
            for (int j = 0; j < 32; j++) {
                float p = __expf(Sr[j] - mx);
                sum += p;
                Pr[j] = tf32r(p);
            }
            sum += __shfl_xor_sync(0xffffffffu, sum, 1);
            if ((t & 1) == 0) {
                float al = __expf(mprev - mx);
                rowL[r] = rowL[r] * al + sum;
                rowM[r] = mx;
                rowA[r] = al;
            }
        }
        __syncthreads();

        // O = O*alpha + P*V
        {
            float a0 = rowA[wrow + g];
            float a1 = rowA[wrow + g + 8];
            #pragma unroll
            for (int ni = 0; ni < 8; ni++) {
                o[ni][0] *= a0; o[ni][1] *= a0;
                o[ni][2] *= a1; o[ni][3] *= a1;
            }
        }
        #pragma unroll
        for (int ks = 0; ks < 64; ks += 8) {
            uint32_t af[4];
            int base = (wrow + g) * AQ_S + ks + t4;
            af[0] = Ss[base];
            af[1] = Ss[base + 8 * AQ_S];
            af[2] = Ss[base + 4];
            af[3] = Ss[base + 8 * AQ_S + 4];
            #pragma unroll
            for (int ni = 0; ni < 8; ni++) {
                uint32_t bf[2];
                bf[0] = Vb[(ks + t4) * AV_S + ni * 8 + g];
                bf[1] = Vb[(ks + t4 + 4) * AV_S + ni * 8 + g];
                mma1688(o[ni], af, bf);
            }
        }
    }

    // Normalize + store (rounded; feeds proj A)
    {
        float inv0 = 1.0f / rowL[wrow + g];
        float inv1 = 1.0f / rowL[wrow + g + 8];
        #pragma unroll
        for (int ni = 0; ni < 8; ni++) {
            int cc = h * 64 + ni * 8 + 2 * t4;
            int r0 = qb + wrow + g;
            float2 lo; lo.x = tf32rf(o[ni][0] * inv0); lo.y = tf32rf(o[ni][1] * inv0);
            float2 hi; hi.x = tf32rf(o[ni][2] * inv1); hi.y = tf32rf(o[ni][3] * inv1);
            *(float2*)(out + (size_t)r0 * EDIM + cc) = lo;
            *(float2*)(out + (size_t)(r0 + 8) * EDIM + cc) = hi;
        }
    }
}

static const int ATTN_SMEM =
    (128 * AQ_S + 2 * K_STG + 2 * V_STG + 128 * AQ_S) * 4 + 3 * 128 * 4;  // 142848

extern "C" void kernel_launch(void* const* d_in, const int* in_sizes, int n_in,
                              void* d_out, int out_size) {
    const float* x      = (const float*)d_in[0];
    const float* ln_g   = (const float*)d_in[1];
    const float* ln_b   = (const float*)d_in[2];
    const float* qkv_w  = (const float*)d_in[3];
    const float* qkv_b  = (const float*)d_in[4];
    const float* proj_w = (const float*)d_in[5];
    const float* proj_b = (const float*)d_in[6];
    const float* fc1_w  = (const float*)d_in[7];
    const float* fc1_b  = (const float*)d_in[8];
    const float* fc2_w  = (const float*)d_in[9];
    const float* fc2_b  = (const float*)d_in[10];
    const float* fc3_w  = (const float*)d_in[11];
    const float* fc3_b  = (const float*)d_in[12];
    float* out = (float*)d_out;

    float *h1, *qkvb, *attnb, *x1, *h2, *m1, *m2;
    float *wqkv, *wproj, *w1, *w2, *w3;
    cudaGetSymbolAddress((void**)&h1, g_h1);
    cudaGetSymbolAddress((void**)&qkvb, g_qkv);
    cudaGetSymbolAddress((void**)&attnb, g_attn);
    cudaGetSymbolAddress((void**)&x1, g_x1);
    cudaGetSymbolAddress((void**)&h2, g_h2);
    cudaGetSymbolAddress((void**)&m1, g_m1);
    cudaGetSymbolAddress((void**)&m2, g_m2);
    cudaGetSymbolAddress((void**)&wqkv, g_wqkv);
    cudaGetSymbolAddress((void**)&wproj, g_wproj);
    cudaGetSymbolAddress((void**)&w1, g_w1);
    cudaGetSymbolAddress((void**)&w2, g_w2);
    cudaGetSymbolAddress((void**)&w3, g_w3);

    cudaFuncSetAttribute(attn_mma_kernel, cudaFuncAttributeMaxDynamicSharedMemorySize,
                         ATTN_SMEM);
    cudaFuncSetAttribute(mma_gemm<128, false, false, true>,
                         cudaFuncAttributeMaxDynamicSharedMemorySize, gemm_smem(128));
    cudaFuncSetAttribute(mma_gemm<64, false, true, false>,
                         cudaFuncAttributeMaxDynamicSharedMemorySize, gemm_smem(64));
    cudaFuncSetAttribute(mma_gemm<128, true, false, true>,
                         cudaFuncAttributeMaxDynamicSharedMemorySize, gemm_smem(128));

    // 0. Pre-round weights to tf32-exact fp32
    round_w_all<<<7168, 256>>>(qkv_w, wqkv, proj_w, wproj, fc1_w, w1,
                               fc2_w, w2, fc3_w, w3);

    // 1. LN1 (rounded output)
    ln_kernel<<<NSEQ, 128>>>(x, ln_g, ln_b, h1);
    // 2. QKV (ROUND=true: qkv buffer is tf32-exact -> attention loads raw bits)
    mma_gemm<128, false, false, true><<<dim3(12, 32), 256, gemm_smem(128)>>>(
        h1, wqkv, qkv_b, nullptr, qkvb, NSEQ, 3 * EDIM, EDIM);
    // 3. Attention
    attn_mma_kernel<<<dim3(32, NHEAD), 256, ATTN_SMEM>>>(qkvb, attnb);
    // 4. proj + residual
    mma_gemm<64, false, true, false><<<dim3(4, 64), 256, gemm_smem(64)>>>(
        attnb, wproj, proj_b, x, x1, NSEQ, EDIM, EDIM);
    // 5. LN2 (rounded output)
    ln_kernel<<<NSEQ, 128>>>(x1, ln_g, ln_b, h2);
    // 6. fc1 + relu (rounded output)
    mma_gemm<128, true, false, true><<<dim3(16, 32), 256, gemm_smem(128)>>>(
        h2, w1, fc1_b, nullptr, m1, NSEQ, HDIM, EDIM);
    // 7. fc2 + relu (rounded output)
    mma_gemm<128, true, false, true><<<dim3(16, 32), 256, gemm_smem(128)>>>(
        m1, w2, fc2_b, nullptr, m2, NSEQ, HDIM, HDIM);
    // 8. fc3 + bias + residual -> out
    mma_gemm<64, false, true, false><<<dim3(4, 64), 256, gemm_smem(64)>>>(
        m2, w3, fc3_b, x1, out, NSEQ, EDIM, HDIM);
}

// round 16
// speedup vs baseline: 2.3098x; 2.3098x over previous
#include <cuda_runtime.h>
#include <cuda_fp16.h>
#include <cstdint>
#include <math.h>

// Problem constants
#define EDIM 512
#define NSEQ 4096
#define NHEAD 8
#define HDIM 2048

// ---- fp16 mma.sync helpers (family-agnostic PTX, works on compute_103) ----
__device__ __forceinline__ void mma16816(float* c, const uint32_t* a, const uint32_t* b) {
    asm volatile(
        "mma.sync.aligned.m16n8k16.row.col.f32.f16.f16.f32 "
        "{%0,%1,%2,%3}, {%4,%5,%6,%7}, {%8,%9}, {%0,%1,%2,%3};"
        : "+f"(c[0]), "+f"(c[1]), "+f"(c[2]), "+f"(c[3])
        : "r"(a[0]), "r"(a[1]), "r"(a[2]), "r"(a[3]), "r"(b[0]), "r"(b[1]));
}
__device__ __forceinline__ void ldsm_x4(uint32_t* r, uint32_t saddr) {
    asm volatile("ldmatrix.sync.aligned.m8n8.x4.shared.b16 {%0,%1,%2,%3}, [%4];"
                 : "=r"(r[0]), "=r"(r[1]), "=r"(r[2]), "=r"(r[3]) : "r"(saddr));
}
__device__ __forceinline__ void ldsm_x4_t(uint32_t* r, uint32_t saddr) {
    asm volatile("ldmatrix.sync.aligned.m8n8.x4.trans.shared.b16 {%0,%1,%2,%3}, [%4];"
                 : "=r"(r[0]), "=r"(r[1]), "=r"(r[2]), "=r"(r[3]) : "r"(saddr));
}
__device__ __forceinline__ uint32_t smem_u32(const void* p) {
    uint32_t a;
    asm("{ .reg .u64 t; cvta.to.shared.u64 t, %1; cvt.u32.u64 %0, t; }" : "=r"(a) : "l"(p));
    return a;
}
__device__ __forceinline__ void cpa16(uint32_t s, const void* g) {
    asm volatile("cp.async.cg.shared.global [%0], [%1], 16;" :: "r"(s), "l"(g));
}
#define CP_COMMIT() asm volatile("cp.async.commit_group;" ::: "memory")
#define CP_WAIT0()  asm volatile("cp.async.wait_group 0;" ::: "memory")
#define CP_WAIT1()  asm volatile("cp.async.wait_group 1;" ::: "memory")

// Scratch (alloc-free rule: __device__ globals)
__device__ __half g_h1[NSEQ * EDIM];
__device__ __half g_qkv[NSEQ * 3 * EDIM];
__device__ __half g_attn[NSEQ * EDIM];
__device__ float  g_x1[NSEQ * EDIM];
__device__ __half g_h2[NSEQ * EDIM];
__device__ __half g_m1[NSEQ * HDIM];
__device__ __half g_m2[NSEQ * HDIM];
// fp16-converted weights
__device__ __half g_wqkv[3 * EDIM * EDIM];
__device__ __half g_wproj[EDIM * EDIM];
__device__ __half g_w1[HDIM * EDIM];
__device__ __half g_w2[HDIM * HDIM];
__device__ __half g_w3[EDIM * HDIM];

// ===========================================================================
// Weight conversion fp32 -> fp16, single fused kernel (float4 units)
//  qkv:196608 | proj:65536 | fc1:262144 | fc2:1048576 | fc3:262144
// ===========================================================================
__global__ void cvt_w_all(const float* __restrict__ s0, __half* __restrict__ d0,
                          const float* __restrict__ s1, __half* __restrict__ d1,
                          const float* __restrict__ s2, __half* __restrict__ d2,
                          const float* __restrict__ s3, __half* __restrict__ d3,
                          const float* __restrict__ s4, __half* __restrict__ d4) {
    int i = blockIdx.x * blockDim.x + threadIdx.x;
    const float* s; __half* d; int off;
    if (i < 196608)       { s = s0; d = d0; off = i; }
    else if (i < 262144)  { s = s1; d = d1; off = i - 196608; }
    else if (i < 524288)  { s = s2; d = d2; off = i - 262144; }
    else if (i < 1572864) { s = s3; d = d3; off = i - 524288; }
    else                  { s = s4; d = d4; off = i - 1572864; }
    float4 v = ((const float4*)s)[off];
    __half2* dp = (__half2*)(d + (size_t)off * 4);
    dp[0] = __floats2half2_rn(v.x, v.y);
    dp[1] = __floats2half2_rn(v.z, v.w);
}

// ===========================================================================
// LayerNorm: fp32 in, fp16 out
// ===========================================================================
__global__ void ln_kernel(const float* __restrict__ X, const float* __restrict__ g,
                          const float* __restrict__ b, __half* __restrict__ Y) {
    const int row = blockIdx.x;
    const int t = threadIdx.x;  // 128 threads
    const float4* Xv = (const float4*)(X + (size_t)row * EDIM);
    float4 v = Xv[t];

    __shared__ float red[4];
    float s = v.x + v.y + v.z + v.w;
    #pragma unroll
    for (int o = 16; o > 0; o >>= 1) s += __shfl_down_sync(0xffffffffu, s, o);
    if ((t & 31) == 0) red[t >> 5] = s;
    __syncthreads();
    float mean = (red[0] + red[1] + red[2] + red[3]) * (1.0f / EDIM);
    __syncthreads();

    float dx = v.x - mean, dy = v.y - mean, dz = v.z - mean, dw = v.w - mean;
    float s2 = dx * dx + dy * dy + dz * dz + dw * dw;
    #pragma unroll
    for (int o = 16; o > 0; o >>= 1) s2 += __shfl_down_sync(0xffffffffu, s2, o);
    if ((t & 31) == 0) red[t >> 5] = s2;
    __syncthreads();
    float var = (red[0] + red[1] + red[2] + red[3]) * (1.0f / EDIM);
    float rs = rsqrtf(var + 1e-5f);

    float4 gv = ((const float4*)g)[t];
    float4 bv = ((const float4*)b)[t];
    __half2* yp = (__half2*)(Y + (size_t)row * EDIM + t * 4);
    yp[0] = __floats2half2_rn(dx * rs * gv.x + bv.x, dy * rs * gv.y + bv.y);
    yp[1] = __floats2half2_rn(dz * rs * gv.z + bv.z, dw * rs * gv.w + bv.w);
}

// ===========================================================================
// fp16 mma.sync GEMM: C[M,N] = A[M,K]*B[N,K]^T (+bias, +res, +relu)
// CTA MTx128, 8 warps, warp tile (MT/2)x32, K-chunk 32 (2 k16 steps),
// 3-stage cp.async; ldmatrix fragment loads. fp32 accumulate + epilogue.
// ===========================================================================
#define SMSH 40   // smem row stride (halves) = 32 + 8 pad

template <int MT, bool RELU, bool RES, bool OUTHALF>
__global__ void __launch_bounds__(256, 2)
mma_gemm(const __half* __restrict__ A, const __half* __restrict__ B,
         const float* __restrict__ bias, const float* __restrict__ Rs,
         void* __restrict__ Cv, int M, int N, int K) {
    constexpr int A_STAGE = MT * SMSH;     // halves
    constexpr int B_STAGE = 128 * SMSH;
    constexpr int MI = MT / 32;
    constexpr int LA = MT / 64;            // A cp.async per thread per chunk

    extern __shared__ __half dsmh[];
    __half* sA = dsmh;
    __half* sB = dsmh + 3 * A_STAGE;

    const int t = threadIdx.x;
    const int wid = t >> 5;
    const int lid = t & 31;
    const int mBase = blockIdx.y * MT;
    const int nBase = blockIdx.x * 128;

    const int wm = (wid >> 2) * (MT / 2);
    const int wn = (wid & 3) * 32;
    const int g = lid >> 2;
    const int t4 = lid & 3;

    float acc[MI][4][4];
    #pragma unroll
    for (int mi = 0; mi < MI; mi++)
        #pragma unroll
        for (int ni = 0; ni < 4; ni++)
            #pragma unroll
            for (int r = 0; r < 4; r++) acc[mi][ni][r] = 0.0f;

    // cp.async loaders: A chunk = MT*4 16B slots, B chunk = 512 slots
    const __half* ApL[LA];
    uint32_t saL[3][LA];
    #pragma unroll
    for (int i = 0; i < LA; i++) {
        int s = t * LA + i;
        int row = s >> 2, q = (s & 3) * 8;   // halves
        ApL[i] = A + (size_t)(mBase + row) * K + q;
        #pragma unroll
        for (int st = 0; st < 3; st++)
            saL[st][i] = smem_u32(&sA[st * A_STAGE + row * SMSH + q]);
    }
    const __half* BpL[2];
    uint32_t sbL[3][2];
    #pragma unroll
    for (int i = 0; i < 2; i++) {
        int s = t * 2 + i;
        int row = s >> 2, q = (s & 3) * 8;
        BpL[i] = B + (size_t)(nBase + row) * K + q;
        #pragma unroll
        for (int st = 0; st < 3; st++)
            sbL[st][i] = smem_u32(&sB[st * B_STAGE + row * SMSH + q]);
    }

    // ldmatrix per-lane base addresses (stage 0)
    const int a_elem = (wm + (lid & 15)) * SMSH + (lid >> 4) * 8;
    const int b_elem = (wn + ((lid >> 4) << 3) + (lid & 7)) * SMSH + ((lid >> 3) & 1) * 8;
    uint32_t aB[3], bB[3];
    #pragma unroll
    for (int st = 0; st < 3; st++) {
        aB[st] = smem_u32(&sA[st * A_STAGE + a_elem]);
        bB[st] = smem_u32(&sB[st * B_STAGE + b_elem]);
    }

    auto issue_chunk = [&](int c, int st) {
        const int k0 = c << 5;   // 32 halves per chunk
        #pragma unroll
        for (int i = 0; i < LA; i++) cpa16(saL[st][i], ApL[i] + k0);
        #pragma unroll
        for (int i = 0; i < 2; i++) cpa16(sbL[st][i], BpL[i] + k0);
    };

    const int T = K >> 5;
    issue_chunk(0, 0); CP_COMMIT();
    if (T > 1) { issue_chunk(1, 1); CP_COMMIT(); }

    int st = 0;
    for (int c = 0; c < T; c++) {
        if (c + 1 < T) CP_WAIT1(); else CP_WAIT0();
        __syncthreads();
        if (c + 2 < T) { issue_chunk(c + 2, (st + 2 >= 3) ? st - 1 : st + 2); CP_COMMIT(); }

        const uint32_t aBs = aB[st];
        const uint32_t bBs = bB[st];
        #pragma unroll
        for (int ks = 0; ks < 32; ks += 16) {
            uint32_t af[MI][4], bfr[2][4];
            #pragma unroll
            for (int mi = 0; mi < MI; mi++)
                ldsm_x4(af[mi], aBs + (mi * 16 * SMSH + ks) * 2);
            #pragma unroll
            for (int nb = 0; nb < 2; nb++)
                ldsm_x4(bfr[nb], bBs + (nb * 16 * SMSH + ks) * 2);
            #pragma unroll
            for (int mi = 0; mi < MI; mi++)
                #pragma unroll
                for (int ni = 0; ni < 4; ni++)
                    mma16816(acc[mi][ni], af[mi], &bfr[ni >> 1][(ni & 1) * 2]);
        }
        st = (st + 1 == 3) ? 0 : st + 1;
    }

    // Epilogue
    #pragma unroll
    for (int mi = 0; mi < MI; mi++) {
        #pragma unroll
        for (int ni = 0; ni < 4; ni++) {
            const int cc = nBase + wn + ni * 8 + 2 * t4;
            const float b0 = bias[cc], b1 = bias[cc + 1];
            #pragma unroll
            for (int h = 0; h < 2; h++) {
                const int row = mBase + wm + mi * 16 + g + h * 8;
                float v0 = acc[mi][ni][2 * h + 0] + b0;
                float v1 = acc[mi][ni][2 * h + 1] + b1;
                if (RES) {
                    const float* rr = Rs + (size_t)row * N + cc;
                    v0 += rr[0]; v1 += rr[1];
                }
                if (RELU) { v0 = fmaxf(v0, 0.0f); v1 = fmaxf(v1, 0.0f); }
                if (OUTHALF) {
                    *(__half2*)((__half*)Cv + (size_t)row * N + cc) =
                        __floats2half2_rn(v0, v1);
                } else {
                    float2 o; o.x = v0; o.y = v1;
                    *(float2*)((float*)Cv + (size_t)row * N + cc) = o;
                }
            }
        }
    }
}

static int gemm_smem(int mt) { return 3 * (mt + 128) * SMSH * 2; }

// ===========================================================================
// fp16 flash attention: 256 threads (8 warps x 16 q-rows), q-block 128,
// K-tile 64 double-buffered cp.async, REGISTER online softmax (quad shfl),
// P half in smem read only by owning warp, V via ldmatrix.trans.
// Softmax scale 0.125 folded into softmax (Q stored unscaled).
// ===========================================================================
#define AH_S 72   // halves stride (64 + 8 pad)
#define KV_STG (64 * AH_S)   // halves per K (or V) buffer

__global__ void __launch_bounds__(256, 2)
attn_mma_kernel(const __half* __restrict__ qkv, __half* __restrict__ out) {
    extern __shared__ __half ash[];
    __half* Qs = ash;                         // 128 x 72
    __half* Ks = Qs + 128 * AH_S;             // 2 x 64 x 72
    __half* Vs = Ks + 2 * KV_STG;             // 2 x 64 x 72
    __half* Ps = Vs + 2 * KV_STG;             // 128 x 72

    const int t = threadIdx.x;      // 256
    const int wid = t >> 5;
    const int lid = t & 31;
    const int g = lid >> 2, t4 = lid & 3;
    const int h = blockIdx.y;
    const int qb = blockIdx.x * 128;
    const int wrow = wid * 16;

    // cp.async Q loader: 1024 16B slots, 4/thread
    {
        #pragma unroll
        for (int i = 0; i < 4; i++) {
            int s = t + 256 * i;
            int r = s >> 3, q = (s & 7) * 8;
            cpa16(smem_u32(&Qs[r * AH_S + q]),
                  qkv + (size_t)(qb + r) * 1536 + h * 64 + q);
        }
    }
    // cp.async K/V loader: 1024 slots per tile (K 512 + V 512), 4/thread
    const __half* gsrc[4];
    uint32_t dst0[4];
    #pragma unroll
    for (int i = 0; i < 4; i++) {
        int s = t + 256 * i;
        int mat = s >> 9;           // 0=K 1=V
        int rem = s & 511;
        int r = rem >> 3, q = (rem & 7) * 8;
        gsrc[i] = qkv + (size_t)r * 1536 + h * 64 + 512 + mat * 512 + q;
        dst0[i] = smem_u32(mat == 0 ? &Ks[r * AH_S + q] : &Vs[r * AH_S + q]);
    }
    auto issue_tile = [&](int kb, int buf) {
        #pragma unroll
        for (int i = 0; i < 4; i++)
            cpa16(dst0[i] + buf * (KV_STG * 2), gsrc[i] + (size_t)kb * 1536);
    };

    issue_tile(0, 0);
    CP_COMMIT();   // group: Q + tile0

    // frag base addresses (halves -> bytes x2)
    const int a_elem = (wrow + (lid & 15)) * AH_S + (lid >> 4) * 8;  // Q / P rows
    const uint32_t qA = smem_u32(&Qs[a_elem]);
    const uint32_t pA = smem_u32(&Ps[a_elem]);
    const int kb_elem = (((lid >> 4) << 3) + (lid & 7)) * AH_S + ((lid >> 3) & 1) * 8;
    const uint32_t kB0 = smem_u32(&Ks[kb_elem]);
    // V trans: addr = (ks + ((lid>>3)&1)*8 + (lid&7)) * AH_S + ((lid>>4)<<3) [+ j*16]
    const int vt_elem = (((lid >> 3) & 1) * 8 + (lid & 7)) * AH_S + ((lid >> 4) << 3);
    const uint32_t vB0 = smem_u32(&Vs[vt_elem]);

    float o[8][4];
    #pragma unroll
    for (int ni = 0; ni < 8; ni++)
        #pragma unroll
        for (int r = 0; r < 4; r++) o[ni][r] = 0.0f;
    float m0 = -1e30f, m1 = -1e30f, l0 = 0.0f, l1 = 0.0f;

    const int NT = NSEQ / 64;
    for (int c = 0; c < NT; c++) {
        const int buf = c & 1;
        CP_WAIT0();
        __syncthreads();   // tile c (and Q on c==0) visible; all warps done with buf
        if (c + 1 < NT) { issue_tile((c + 1) * 64, buf ^ 1); CP_COMMIT(); }

        const uint32_t kBb = kB0 + buf * (KV_STG * 2);
        const uint32_t vBb = vB0 + buf * (KV_STG * 2);

        // ---- S = Q*K^T (fp32 frags) ----
        float sf[8][4];
        #pragma unroll
        for (int ni = 0; ni < 8; ni++)
            #pragma unroll
            for (int r = 0; r < 4; r++) sf[ni][r] = 0.0f;

        #pragma unroll
        for (int ks = 0; ks < 64; ks += 16) {
            uint32_t af[4];
            ldsm_x4(af, qA + ks * 2);
            #pragma unroll
            for (int j = 0; j < 4; j++) {       // key-blocks of 16
                uint32_t bfr[4];
                ldsm_x4(bfr, kBb + (j * 16 * AH_S + ks) * 2);
                mma16816(sf[2 * j + 0], af, &bfr[0]);
                mma16816(sf[2 * j + 1], af, &bfr[2]);
            }
        }

        // ---- register online softmax (rows wrow+g, wrow+g+8; quad-shared) ----
        {
            float mx0 = -1e30f, mx1 = -1e30f;
            #pragma unroll
            for (int ni = 0; ni < 8; ni++) {
                mx0 = fmaxf(mx0, fmaxf(sf[ni][0], sf[ni][1]));
                mx1 = fmaxf(mx1, fmaxf(sf[ni][2], sf[ni][3]));
            }
            mx0 *= 0.125f; mx1 *= 0.125f;
            mx0 = fmaxf(mx0, __shfl_xor_sync(0xffffffffu, mx0, 1));
            mx0 = fmaxf(mx0, __shfl_xor_sync(0xffffffffu, mx0, 2));
            mx1 = fmaxf(mx1, __shfl_xor_sync(0xffffffffu, mx1, 1));
            mx1 = fmaxf(mx1, __shfl_xor_sync(0xffffffffu, mx1, 2));
            float m0n = fmaxf(m0, mx0), m1n = fmaxf(m1, mx1);
            float al0 = __expf(m0 - m0n), al1 = __expf(m1 - m1n);
            float s0 = 0.0f, s1 = 0.0f;
            __half* Pr0 = Ps + (wrow + g) * AH_S + 2 * t4;
            __half* Pr1 = Ps + (wrow + g + 8) * AH_S + 2 * t4;
            #pragma unroll
            for (int ni = 0; ni < 8; ni++) {
                float p00 = __expf(sf[ni][0] * 0.125f - m0n);
                float p01 = __expf(sf[ni][1] * 0.125f - m0n);
                float p10 = __expf(sf[ni][2] * 0.125f - m1n);
                float p11 = __expf(sf[ni][3] * 0.125f - m1n);
                s0 += p00 + p01; s1 += p10 + p11;
                *(__half2*)(Pr0 + ni * 8) = __floats2half2_rn(p00, p01);
                *(__half2*)(Pr1 + ni * 8) = __floats2half2_rn(p10, p11);
            }
            s0 += __shfl_xor_sync(0xffffffffu, s0, 1);
            s0 += __shfl_xor_sync(0xffffffffu, s0, 2);
            s1 += __shfl_xor_sync(0xffffffffu, s1, 1);
            s1 += __shfl_xor_sync(0xffffffffu, s1, 2);
            l0 = l0 * al0 + s0; l1 = l1 * al1 + s1;
            m0 = m0n; m1 = m1n;
            #pragma unroll
            for (int ni = 0; ni < 8; ni++) {
                o[ni][0] *= al0; o[ni][1] *= al0;
                o[ni][2] *= al1; o[ni][3] *= al1;
            }
        }
        __syncwarp();   // P stores visible to own warp's ldmatrix

        // ---- O += P*V (V via ldmatrix.trans) ----
        #pragma unroll
        for (int ks = 0; ks < 64; ks += 16) {
            uint32_t af[4];
            ldsm_x4(af, pA + ks * 2);
            #pragma unroll
            for (int j = 0; j < 4; j++) {       // d-block pairs (16 cols)
                uint32_t bfr[4];
                ldsm_x4_t(bfr, vBb + (ks * AH_S + j * 16) * 2);
                mma16816(o[2 * j + 0], af, &bfr[0]);
                mma16816(o[2 * j + 1], af, &bfr[2]);
            }
        }
    }

    // Normalize + store half (feeds proj A)
    {
        float inv0 = 1.0f / l0, inv1 = 1.0f / l1;
        #pragma unroll
        for (int ni = 0; ni < 8; ni++) {
            int cc = h * 64 + ni * 8 + 2 * t4;
            int r0 = qb + wrow + g;
            *(__half2*)(out + (size_t)r0 * EDIM + cc) =
                __floats2half2_rn(o[ni][0] * inv0, o[ni][1] * inv0);
            *(__half2*)(out + (size_t)(r0 + 8) * EDIM + cc) =
                __floats2half2_rn(o[ni][2] * inv1, o[ni][3] * inv1);
        }
    }
}

static const int ATTN_SMEM = (128 * AH_S + 4 * KV_STG + 128 * AH_S) * 2;  // 73728

extern "C" void kernel_launch(void* const* d_in, const int* in_sizes, int n_in,
                              void* d_out, int out_size) {
    const float* x      = (const float*)d_in[0];
    const float* ln_g   = (const float*)d_in[1];
    const float* ln_b   = (const float*)d_in[2];
    const float* qkv_w  = (const float*)d_in[3];
    const float* qkv_b  = (const float*)d_in[4];
    const float* proj_w = (const float*)d_in[5];
    const float* proj_b = (const float*)d_in[6];
    const float* fc1_w  = (const float*)d_in[7];
    const float* fc1_b  = (const float*)d_in[8];
    const float* fc2_w  = (const float*)d_in[9];
    const float* fc2_b  = (const float*)d_in[10];
    const float* fc3_w  = (const float*)d_in[11];
    const float* fc3_b  = (const float*)d_in[12];
    float* out = (float*)d_out;

    __half *h1, *qkvb, *attnb, *h2, *m1, *m2;
    __half *wqkv, *wproj, *w1, *w2, *w3;
    float *x1;
    cudaGetSymbolAddress((void**)&h1, g_h1);
    cudaGetSymbolAddress((void**)&qkvb, g_qkv);
    cudaGetSymbolAddress((void**)&attnb, g_attn);
    cudaGetSymbolAddress((void**)&x1, g_x1);
    cudaGetSymbolAddress((void**)&h2, g_h2);
    cudaGetSymbolAddress((void**)&m1, g_m1);
    cudaGetSymbolAddress((void**)&m2, g_m2);
    cudaGetSymbolAddress((void**)&wqkv, g_wqkv);
    cudaGetSymbolAddress((void**)&wproj, g_wproj);
    cudaGetSymbolAddress((void**)&w1, g_w1);
    cudaGetSymbolAddress((void**)&w2, g_w2);
    cudaGetSymbolAddress((void**)&w3, g_w3);

    cudaFuncSetAttribute(attn_mma_kernel, cudaFuncAttributeMaxDynamicSharedMemorySize,
                         ATTN_SMEM);
    cudaFuncSetAttribute(mma_gemm<128, false, false, true>,
                         cudaFuncAttributeMaxDynamicSharedMemorySize, gemm_smem(128));
    cudaFuncSetAttribute(mma_gemm<64, false, true, false>,
                         cudaFuncAttributeMaxDynamicSharedMemorySize, gemm_smem(64));
    cudaFuncSetAttribute(mma_gemm<128, true, false, true>,
                         cudaFuncAttributeMaxDynamicSharedMemorySize, gemm_smem(128));

    // 0. Convert weights fp32 -> fp16
    cvt_w_all<<<7168, 256>>>(qkv_w, wqkv, proj_w, wproj, fc1_w, w1,
                             fc2_w, w2, fc3_w, w3);

    // 1. LN1 -> half
    ln_kernel<<<NSEQ, 128>>>(x, ln_g, ln_b, h1);
    // 2. QKV: [4096,512]x[1536,512]^T -> half
    mma_gemm<128, false, false, true><<<dim3(12, 32), 256, gemm_smem(128)>>>(
        h1, wqkv, qkv_b, nullptr, qkvb, NSEQ, 3 * EDIM, EDIM);
    // 3. Attention -> half
    attn_mma_kernel<<<dim3(32, NHEAD), 256, ATTN_SMEM>>>(qkvb, attnb);
    // 4. proj + residual -> fp32
    mma_gemm<64, false, true, false><<<dim3(4, 64), 256, gemm_smem(64)>>>(
        attnb, wproj, proj_b, x, x1, NSEQ, EDIM, EDIM);
    // 5. LN2 -> half
    ln_kernel<<<NSEQ, 128>>>(x1, ln_g, ln_b, h2);
    // 6. fc1 + relu -> half
    mma_gemm<128, true, false, true><<<dim3(16, 32), 256, gemm_smem(128)>>>(
        h2, w1, fc1_b, nullptr, m1, NSEQ, HDIM, EDIM);
    // 7. fc2 + relu -> half
    mma_gemm<128, true, false, true><<<dim3(16, 32), 256, gemm_smem(128)>>>(
        m1, w2, fc2_b, nullptr, m2, NSEQ, HDIM, HDIM);
    // 8. fc3 + bias + residual -> fp32 out
    mma_gemm<64, false, true, false><<<dim3(4, 64), 256, gemm_smem(64)>>>(
        m2, w3, fc3_b, x1, out, NSEQ, EDIM, HDIM);
}

// round 17
// speedup vs baseline: 2.7622x; 1.1958x over previous
#include <cuda_runtime.h>
#include <cuda_fp16.h>
#include <cstdint>
#include <math.h>

// Problem constants
#define EDIM 512
#define NSEQ 4096
#define NHEAD 8
#define HDIM 2048

// 0.125 * log2(e): folded into Q weights/bias so softmax is a bare ex2
#define QSCALE 0.18033688011112042f

// ---- fp16 mma.sync helpers (family-agnostic PTX, works on compute_103) ----
__device__ __forceinline__ void mma16816(float* c, const uint32_t* a, const uint32_t* b) {
    asm volatile(
        "mma.sync.aligned.m16n8k16.row.col.f32.f16.f16.f32 "
        "{%0,%1,%2,%3}, {%4,%5,%6,%7}, {%8,%9}, {%0,%1,%2,%3};"
        : "+f"(c[0]), "+f"(c[1]), "+f"(c[2]), "+f"(c[3])
        : "r"(a[0]), "r"(a[1]), "r"(a[2]), "r"(a[3]), "r"(b[0]), "r"(b[1]));
}
__device__ __forceinline__ void ldsm_x4(uint32_t* r, uint32_t saddr) {
    asm volatile("ldmatrix.sync.aligned.m8n8.x4.shared.b16 {%0,%1,%2,%3}, [%4];"
                 : "=r"(r[0]), "=r"(r[1]), "=r"(r[2]), "=r"(r[3]) : "r"(saddr));
}
__device__ __forceinline__ void ldsm_x4_t(uint32_t* r, uint32_t saddr) {
    asm volatile("ldmatrix.sync.aligned.m8n8.x4.trans.shared.b16 {%0,%1,%2,%3}, [%4];"
                 : "=r"(r[0]), "=r"(r[1]), "=r"(r[2]), "=r"(r[3]) : "r"(saddr));
}
__device__ __forceinline__ uint32_t smem_u32(const void* p) {
    uint32_t a;
    asm("{ .reg .u64 t; cvta.to.shared.u64 t, %1; cvt.u32.u64 %0, t; }" : "=r"(a) : "l"(p));
    return a;
}
__device__ __forceinline__ void cpa16(uint32_t s, const void* g) {
    asm volatile("cp.async.cg.shared.global [%0], [%1], 16;" :: "r"(s), "l"(g));
}
__device__ __forceinline__ float ex2(float x) {
    float y;
    asm("ex2.approx.f32 %0, %1;" : "=f"(y) : "f"(x));
    return y;
}
#define CP_COMMIT() asm volatile("cp.async.commit_group;" ::: "memory")
#define CP_WAIT0()  asm volatile("cp.async.wait_group 0;" ::: "memory")
#define CP_WAIT1()  asm volatile("cp.async.wait_group 1;" ::: "memory")

// Scratch (alloc-free rule: __device__ globals)
__device__ __half g_h1[NSEQ * EDIM];
__device__ __half g_qkv[NSEQ * 3 * EDIM];
__device__ __half g_attn[NSEQ * EDIM];
__device__ float  g_x1[NSEQ * EDIM];
__device__ __half g_h2[NSEQ * EDIM];
__device__ __half g_m1[NSEQ * HDIM];
__device__ __half g_m2[NSEQ * HDIM];
// fp16-converted weights (+ scaled fp32 qkv bias)
__device__ __half g_wqkv[3 * EDIM * EDIM];
__device__ __half g_wproj[EDIM * EDIM];
__device__ __half g_w1[HDIM * EDIM];
__device__ __half g_w2[HDIM * HDIM];
__device__ __half g_w3[EDIM * HDIM];
__device__ float  g_qb[3 * EDIM];

// ===========================================================================
// Weight conversion fp32 -> fp16, single fused kernel (float4 units).
// Q-rows of qkv_w (rows<512 <=> off<65536) and Q part of qkv_b scaled by
// QSCALE so attention softmax uses ex2 directly.
//  qkv:196608 | proj:65536 | fc1:262144 | fc2:1048576 | fc3:262144 | +bias
// ===========================================================================
__global__ void cvt_w_all(const float* __restrict__ s0, __half* __restrict__ d0,
                          const float* __restrict__ s1, __half* __restrict__ d1,
                          const float* __restrict__ s2, __half* __restrict__ d2,
                          const float* __restrict__ s3, __half* __restrict__ d3,
                          const float* __restrict__ s4, __half* __restrict__ d4,
                          const float* __restrict__ qb_src, float* __restrict__ qb_dst) {
    int i = blockIdx.x * blockDim.x + threadIdx.x;
    if (i >= 1835008) {
        int j = i - 1835008;
        if (j < 384) {
            float4 v = ((const float4*)qb_src)[j];
            if (j < 128) { v.x *= QSCALE; v.y *= QSCALE; v.z *= QSCALE; v.w *= QSCALE; }
            ((float4*)qb_dst)[j] = v;
        }
        return;
    }
    const float* s; __half* d; int off; bool sc = false;
    if (i < 196608)       { s = s0; d = d0; off = i; sc = (i < 65536); }
    else if (i < 262144)  { s = s1; d = d1; off = i - 196608; }
    else if (i < 524288)  { s = s2; d = d2; off = i - 262144; }
    else if (i < 1572864) { s = s3; d = d3; off = i - 524288; }
    else                  { s = s4; d = d4; off = i - 1572864; }
    float4 v = ((const float4*)s)[off];
    if (sc) { v.x *= QSCALE; v.y *= QSCALE; v.z *= QSCALE; v.w *= QSCALE; }
    __half2* dp = (__half2*)(d + (size_t)off * 4);
    dp[0] = __floats2half2_rn(v.x, v.y);
    dp[1] = __floats2half2_rn(v.z, v.w);
}

// ===========================================================================
// LayerNorm: fp32 in, fp16 out
// ===========================================================================
__global__ void ln_kernel(const float* __restrict__ X, const float* __restrict__ g,
                          const float* __restrict__ b, __half* __restrict__ Y) {
    const int row = blockIdx.x;
    const int t = threadIdx.x;  // 128 threads
    const float4* Xv = (const float4*)(X + (size_t)row * EDIM);
    float4 v = Xv[t];

    __shared__ float red[4];
    float s = v.x + v.y + v.z + v.w;
    #pragma unroll
    for (int o = 16; o > 0; o >>= 1) s += __shfl_down_sync(0xffffffffu, s, o);
    if ((t & 31) == 0) red[t >> 5] = s;
    __syncthreads();
    float mean = (red[0] + red[1] + red[2] + red[3]) * (1.0f / EDIM);
    __syncthreads();

    float dx = v.x - mean, dy = v.y - mean, dz = v.z - mean, dw = v.w - mean;
    float s2 = dx * dx + dy * dy + dz * dz + dw * dw;
    #pragma unroll
    for (int o = 16; o > 0; o >>= 1) s2 += __shfl_down_sync(0xffffffffu, s2, o);
    if ((t & 31) == 0) red[t >> 5] = s2;
    __syncthreads();
    float var = (red[0] + red[1] + red[2] + red[3]) * (1.0f / EDIM);
    float rs = rsqrtf(var + 1e-5f);

    float4 gv = ((const float4*)g)[t];
    float4 bv = ((const float4*)b)[t];
    __half2* yp = (__half2*)(Y + (size_t)row * EDIM + t * 4);
    yp[0] = __floats2half2_rn(dx * rs * gv.x + bv.x, dy * rs * gv.y + bv.y);
    yp[1] = __floats2half2_rn(dz * rs * gv.z + bv.z, dw * rs * gv.w + bv.w);
}

// ===========================================================================
// fp16 mma.sync GEMM: C[M,N] = A[M,K]*B[N,K]^T (+bias, +res, +relu)
// CTA MTx128, 8 warps, warp tile (MT/2)x32, K-chunk 64 halves (4 k16 steps),
// 3-stage cp.async; ldmatrix fragment loads; fp32 accumulate + epilogue.
// ===========================================================================
#define SMSH 72   // smem row stride (halves) = 64 + 8 pad

template <int MT, bool RELU, bool RES, bool OUTHALF>
__global__ void __launch_bounds__(256, 2)
mma_gemm(const __half* __restrict__ A, const __half* __restrict__ B,
         const float* __restrict__ bias, const float* __restrict__ Rs,
         void* __restrict__ Cv, int M, int N, int K) {
    constexpr int A_STAGE = MT * SMSH;     // halves
    constexpr int B_STAGE = 128 * SMSH;
    constexpr int MI = MT / 32;            // A fragments per warp
    constexpr int LA = MT / 32;            // A cp.async per thread per chunk
    constexpr int ISTEP = 32 * SMSH * 2;   // bytes between loader row-groups

    extern __shared__ __half dsmh[];
    __half* sA = dsmh;
    __half* sB = dsmh + 3 * A_STAGE;

    const int t = threadIdx.x;
    const int wid = t >> 5;
    const int lid = t & 31;
    const int mBase = blockIdx.y * MT;
    const int nBase = blockIdx.x * 128;

    const int wm = (wid >> 2) * (MT / 2);
    const int wn = (wid & 3) * 32;
    const int g = lid >> 2;
    const int t4 = lid & 3;

    float acc[MI][4][4];
    #pragma unroll
    for (int mi = 0; mi < MI; mi++)
        #pragma unroll
        for (int ni = 0; ni < 4; ni++)
            #pragma unroll
            for (int r = 0; r < 4; r++) acc[mi][ni][r] = 0.0f;

    // Affine cp.async loader: slot s = t + 256*i -> row = (t>>3) + 32*i,
    // quad = (t&7)*8 halves. A: LA rows/thread, B: 4 rows/thread.
    const int r0 = t >> 3;
    const int qh = (t & 7) * 8;
    const __half* Ap = A + (size_t)(mBase + r0) * K + qh;
    const __half* Bp = B + (size_t)(nBase + r0) * K + qh;
    uint32_t saB[3], sbB[3];
    #pragma unroll
    for (int st = 0; st < 3; st++) {
        saB[st] = smem_u32(&sA[st * A_STAGE + r0 * SMSH + qh]);
        sbB[st] = smem_u32(&sB[st * B_STAGE + r0 * SMSH + qh]);
    }

    // ldmatrix per-lane base addresses (stage 0)
    const int a_elem = (wm + (lid & 15)) * SMSH + (lid >> 4) * 8;
    const int b_elem = (wn + ((lid >> 4) << 3) + (lid & 7)) * SMSH + ((lid >> 3) & 1) * 8;
    uint32_t aB[3], bB[3];
    #pragma unroll
    for (int st = 0; st < 3; st++) {
        aB[st] = smem_u32(&sA[st * A_STAGE + a_elem]);
        bB[st] = smem_u32(&sB[st * B_STAGE + b_elem]);
    }

    auto issue_chunk = [&](int c, int st) {
        const int k0 = c << 6;   // 64 halves per chunk
        #pragma unroll
        for (int i = 0; i < LA; i++)
            cpa16(saB[st] + i * ISTEP, Ap + k0 + (size_t)(32 * i) * K);
        #pragma unroll
        for (int i = 0; i < 4; i++)
            cpa16(sbB[st] + i * ISTEP, Bp + k0 + (size_t)(32 * i) * K);
    };

    const int T = K >> 6;
    issue_chunk(0, 0); CP_COMMIT();
    if (T > 1) { issue_chunk(1, 1); CP_COMMIT(); }

    int st = 0;
    for (int c = 0; c < T; c++) {
        if (c + 1 < T) CP_WAIT1(); else CP_WAIT0();
        __syncthreads();
        if (c + 2 < T) { issue_chunk(c + 2, (st + 2 >= 3) ? st - 1 : st + 2); CP_COMMIT(); }

        const uint32_t aBs = aB[st];
        const uint32_t bBs = bB[st];
        #pragma unroll
        for (int ks = 0; ks < 64; ks += 16) {
            uint32_t af[MI][4], bfr[2][4];
            #pragma unroll
            for (int mi = 0; mi < MI; mi++)
                ldsm_x4(af[mi], aBs + (mi * 16 * SMSH + ks) * 2);
            #pragma unroll
            for (int nb = 0; nb < 2; nb++)
                ldsm_x4(bfr[nb], bBs + (nb * 16 * SMSH + ks) * 2);
            #pragma unroll
            for (int mi = 0; mi < MI; mi++)
                #pragma unroll
                for (int ni = 0; ni < 4; ni++)
                    mma16816(acc[mi][ni], af[mi], &bfr[ni >> 1][(ni & 1) * 2]);
        }
        st = (st + 1 == 3) ? 0 : st + 1;
    }

    // Epilogue
    #pragma unroll
    for (int mi = 0; mi < MI; mi++) {
        #pragma unroll
        for (int ni = 0; ni < 4; ni++) {
            const int cc = nBase + wn + ni * 8 + 2 * t4;
            const float b0 = bias[cc], b1 = bias[cc + 1];
            #pragma unroll
            for (int h = 0; h < 2; h++) {
                const int row = mBase + wm + mi * 16 + g + h * 8;
                float v0 = acc[mi][ni][2 * h + 0] + b0;
                float v1 = acc[mi][ni][2 * h + 1] + b1;
                if (RES) {
                    const float* rr = Rs + (size_t)row * N + cc;
                    v0 += rr[0]; v1 += rr[1];
                }
                if (RELU) { v0 = fmaxf(v0, 0.0f); v1 = fmaxf(v1, 0.0f); }
                if (OUTHALF) {
                    *(__half2*)((__half*)Cv + (size_t)row * N + cc) =
                        __floats2half2_rn(v0, v1);
                } else {
                    float2 o; o.x = v0; o.y = v1;
                    *(float2*)((float*)Cv + (size_t)row * N + cc) = o;
                }
            }
        }
    }
}

static int gemm_smem(int mt) { return 3 * (mt + 128) * SMSH * 2; }

// ===========================================================================
// fp16 flash attention: 256 threads (8 warps x 16 q-rows), q-block 128,
// K-tile 64 double-buffered cp.async, register online softmax (quad shfl).
// Q pre-scaled by 0.125*log2e (folded into weights) -> softmax is bare ex2.
// ===========================================================================
#define AH_S 72   // halves stride (64 + 8 pad)
#define KV_STG (64 * AH_S)   // halves per K (or V) buffer

__global__ void __launch_bounds__(256, 2)
attn_mma_kernel(const __half* __restrict__ qkv, __half* __restrict__ out) {
    extern __shared__ __half ash[];
    __half* Qs = ash;                         // 128 x 72
    __half* Ks = Qs + 128 * AH_S;             // 2 x 64 x 72
    __half* Vs = Ks + 2 * KV_STG;             // 2 x 64 x 72
    __half* Ps = Vs + 2 * KV_STG;             // 128 x 72

    const int t = threadIdx.x;      // 256
    const int wid = t >> 5;
    const int lid = t & 31;
    const int g = lid >> 2, t4 = lid & 3;
    const int h = blockIdx.y;
    const int qb = blockIdx.x * 128;
    const int wrow = wid * 16;

    // cp.async Q loader: 1024 16B slots, 4/thread
    {
        #pragma unroll
        for (int i = 0; i < 4; i++) {
            int s = t + 256 * i;
            int r = s >> 3, q = (s & 7) * 8;
            cpa16(smem_u32(&Qs[r * AH_S + q]),
                  qkv + (size_t)(qb + r) * 1536 + h * 64 + q);
        }
    }
    // cp.async K/V loader: 1024 slots per tile (K 512 + V 512), 4/thread
    const __half* gsrc[4];
    uint32_t dst0[4];
    #pragma unroll
    for (int i = 0; i < 4; i++) {
        int s = t + 256 * i;
        int mat = s >> 9;           // 0=K 1=V
        int rem = s & 511;
        int r = rem >> 3, q = (rem & 7) * 8;
        gsrc[i] = qkv + (size_t)r * 1536 + h * 64 + 512 + mat * 512 + q;
        dst0[i] = smem_u32(mat == 0 ? &Ks[r * AH_S + q] : &Vs[r * AH_S + q]);
    }
    auto issue_tile = [&](int kb, int buf) {
        #pragma unroll
        for (int i = 0; i < 4; i++)
            cpa16(dst0[i] + buf * (KV_STG * 2), gsrc[i] + (size_t)kb * 1536);
    };

    issue_tile(0, 0);
    CP_COMMIT();   // group: Q + tile0

    // frag base addresses
    const int a_elem = (wrow + (lid & 15)) * AH_S + (lid >> 4) * 8;  // Q / P rows
    const uint32_t qA = smem_u32(&Qs[a_elem]);
    const uint32_t pA = smem_u32(&Ps[a_elem]);
    const int kb_elem = (((lid >> 4) << 3) + (lid & 7)) * AH_S + ((lid >> 3) & 1) * 8;
    const uint32_t kB0 = smem_u32(&Ks[kb_elem]);
    const int vt_elem = (((lid >> 3) & 1) * 8 + (lid & 7)) * AH_S + ((lid >> 4) << 3);
    const uint32_t vB0 = smem_u32(&Vs[vt_elem]);

    float o[8][4];
    #pragma unroll
    for (int ni = 0; ni < 8; ni++)
        #pragma unroll
        for (int r = 0; r < 4; r++) o[ni][r] = 0.0f;
    float m0 = -1e30f, m1 = -1e30f, l0 = 0.0f, l1 = 0.0f;

    const int NT = NSEQ / 64;
    for (int c = 0; c < NT; c++) {
        const int buf = c & 1;
        CP_WAIT0();
        __syncthreads();   // tile c (and Q on c==0) visible; all warps done with buf
        if (c + 1 < NT) { issue_tile((c + 1) * 64, buf ^ 1); CP_COMMIT(); }

        const uint32_t kBb = kB0 + buf * (KV_STG * 2);
        const uint32_t vBb = vB0 + buf * (KV_STG * 2);

        // ---- S = Q*K^T (fp32 frags, already in log2 domain) ----
        float sf[8][4];
        #pragma unroll
        for (int ni = 0; ni < 8; ni++)
            #pragma unroll
            for (int r = 0; r < 4; r++) sf[ni][r] = 0.0f;

        #pragma unroll
        for (int ks = 0; ks < 64; ks += 16) {
            uint32_t af[4];
            ldsm_x4(af, qA + ks * 2);
            #pragma unroll
            for (int j = 0; j < 4; j++) {       // key-blocks of 16
                uint32_t bfr[4];
                ldsm_x4(bfr, kBb + (j * 16 * AH_S + ks) * 2);
                mma16816(sf[2 * j + 0], af, &bfr[0]);
                mma16816(sf[2 * j + 1], af, &bfr[2]);
            }
        }

        // ---- register online softmax (rows wrow+g, wrow+g+8; quad-shared) ----
        {
            float mx0 = -1e30f, mx1 = -1e30f;
            #pragma unroll
            for (int ni = 0; ni < 8; ni++) {
                mx0 = fmaxf(mx0, fmaxf(sf[ni][0], sf[ni][1]));
                mx1 = fmaxf(mx1, fmaxf(sf[ni][2], sf[ni][3]));
            }
            mx0 = fmaxf(mx0, __shfl_xor_sync(0xffffffffu, mx0, 1));
            mx0 = fmaxf(mx0, __shfl_xor_sync(0xffffffffu, mx0, 2));
            mx1 = fmaxf(mx1, __shfl_xor_sync(0xffffffffu, mx1, 1));
            mx1 = fmaxf(mx1, __shfl_xor_sync(0xffffffffu, mx1, 2));
            float m0n = fmaxf(m0, mx0), m1n = fmaxf(m1, mx1);
            float al0 = ex2(m0 - m0n), al1 = ex2(m1 - m1n);
            float s0 = 0.0f, s1 = 0.0f;
            __half* Pr0 = Ps + (wrow + g) * AH_S + 2 * t4;
            __half* Pr1 = Ps + (wrow + g + 8) * AH_S + 2 * t4;
            #pragma unroll
            for (int ni = 0; ni < 8; ni++) {
                float p00 = ex2(sf[ni][0] - m0n);
                float p01 = ex2(sf[ni][1] - m0n);
                float p10 = ex2(sf[ni][2] - m1n);
                float p11 = ex2(sf[ni][3] - m1n);
                s0 += p00 + p01; s1 += p10 + p11;
                *(__half2*)(Pr0 + ni * 8) = __floats2half2_rn(p00, p01);
                *(__half2*)(Pr1 + ni * 8) = __floats2half2_rn(p10, p11);
            }
            s0 += __shfl_xor_sync(0xffffffffu, s0, 1);
            s0 += __shfl_xor_sync(0xffffffffu, s0, 2);
            s1 += __shfl_xor_sync(0xffffffffu, s1, 1);
            s1 += __shfl_xor_sync(0xffffffffu, s1, 2);
            l0 = l0 * al0 + s0; l1 = l1 * al1 + s1;
            m0 = m0n; m1 = m1n;
            #pragma unroll
            for (int ni = 0; ni < 8; ni++) {
                o[ni][0] *= al0; o[ni][1] *= al0;
                o[ni][2] *= al1; o[ni][3] *= al1;
            }
        }
        __syncwarp();   // P stores visible to own warp's ldmatrix

        // ---- O += P*V (V via ldmatrix.trans) ----
        #pragma unroll
        for (int ks = 0; ks < 64; ks += 16) {
            uint32_t af[4];
            ldsm_x4(af, pA + ks * 2);
            #pragma unroll
            for (int j = 0; j < 4; j++) {       // d-block pairs (16 cols)
                uint32_t bfr[4];
                ldsm_x4_t(bfr, vBb + (ks * AH_S + j * 16) * 2);
                mma16816(o[2 * j + 0], af, &bfr[0]);
                mma16816(o[2 * j + 1], af, &bfr[2]);
            }
        }
    }

    // Normalize + store half (feeds proj A)
    {
        float inv0 = 1.0f / l0, inv1 = 1.0f / l1;
        #pragma unroll
        for (int ni = 0; ni < 8; ni++) {
            int cc = h * 64 + ni * 8 + 2 * t4;
            int r0 = qb + wrow + g;
            *(__half2*)(out + (size_t)r0 * EDIM + cc) =
                __floats2half2_rn(o[ni][0] * inv0, o[ni][1] * inv0);
            *(__half2*)(out + (size_t)(r0 + 8) * EDIM + cc) =
                __floats2half2_rn(o[ni][2] * inv1, o[ni][3] * inv1);
        }
    }
}

static const int ATTN_SMEM = (128 * AH_S + 4 * KV_STG + 128 * AH_S) * 2;  // 73728

extern "C" void kernel_launch(void* const* d_in, const int* in_sizes, int n_in,
                              void* d_out, int out_size) {
    const float* x      = (const float*)d_in[0];
    const float* ln_g   = (const float*)d_in[1];
    const float* ln_b   = (const float*)d_in[2];
    const float* qkv_w  = (const float*)d_in[3];
    const float* qkv_b  = (const float*)d_in[4];
    const float* proj_w = (const float*)d_in[5];
    const float* proj_b = (const float*)d_in[6];
    const float* fc1_w  = (const float*)d_in[7];
    const float* fc1_b  = (const float*)d_in[8];
    const float* fc2_w  = (const float*)d_in[9];
    const float* fc2_b  = (const float*)d_in[10];
    const float* fc3_w  = (const float*)d_in[11];
    const float* fc3_b  = (const float*)d_in[12];
    float* out = (float*)d_out;

    __half *h1, *qkvb, *attnb, *h2, *m1, *m2;
    __half *wqkv, *wproj, *w1, *w2, *w3;
    float *x1, *qb;
    cudaGetSymbolAddress((void**)&h1, g_h1);
    cudaGetSymbolAddress((void**)&qkvb, g_qkv);
    cudaGetSymbolAddress((void**)&attnb, g_attn);
    cudaGetSymbolAddress((void**)&x1, g_x1);
    cudaGetSymbolAddress((void**)&h2, g_h2);
    cudaGetSymbolAddress((void**)&m1, g_m1);
    cudaGetSymbolAddress((void**)&m2, g_m2);
    cudaGetSymbolAddress((void**)&wqkv, g_wqkv);
    cudaGetSymbolAddress((void**)&wproj, g_wproj);
    cudaGetSymbolAddress((void**)&w1, g_w1);
    cudaGetSymbolAddress((void**)&w2, g_w2);
    cudaGetSymbolAddress((void**)&w3, g_w3);
    cudaGetSymbolAddress((void**)&qb, g_qb);

    cudaFuncSetAttribute(attn_mma_kernel, cudaFuncAttributeMaxDynamicSharedMemorySize,
                         ATTN_SMEM);
    cudaFuncSetAttribute(mma_gemm<128, false, false, true>,
                         cudaFuncAttributeMaxDynamicSharedMemorySize, gemm_smem(128));
    cudaFuncSetAttribute(mma_gemm<64, false, true, false>,
                         cudaFuncAttributeMaxDynamicSharedMemorySize, gemm_smem(64));
    cudaFuncSetAttribute(mma_gemm<128, true, false, true>,
                         cudaFuncAttributeMaxDynamicSharedMemorySize, gemm_smem(128));

    // 0. Convert weights fp32 -> fp16 (Q rows scaled by 0.125*log2e) + bias
    cvt_w_all<<<7170, 256>>>(qkv_w, wqkv, proj_w, wproj, fc1_w, w1,
                             fc2_w, w2, fc3_w, w3, qkv_b, qb);

    // 1. LN1 -> half
    ln_kernel<<<NSEQ, 128>>>(x, ln_g, ln_b, h1);
    // 2. QKV -> half (Q pre-scaled via weights/bias)
    mma_gemm<128, false, false, true><<<dim3(12, 32), 256, gemm_smem(128)>>>(
        h1, wqkv, qb, nullptr, qkvb, NSEQ, 3 * EDIM, EDIM);
    // 3. Attention -> half
    attn_mma_kernel<<<dim3(32, NHEAD), 256, ATTN_SMEM>>>(qkvb, attnb);
    // 4. proj + residual -> fp32
    mma_gemm<64, false, true, false><<<dim3(4, 64), 256, gemm_smem(64)>>>(
        attnb, wproj, proj_b, x, x1, NSEQ, EDIM, EDIM);
    // 5. LN2 -> half
    ln_kernel<<<NSEQ, 128>>>(x1, ln_g, ln_b, h2);
    // 6. fc1 + relu -> half
    mma_gemm<128, true, false, true><<<dim3(16, 32), 256, gemm_smem(128)>>>(
        h2, w1, fc1_b, nullptr, m1, NSEQ, HDIM, EDIM);
    // 7. fc2 + relu -> half
    mma_gemm<128, true, false, true><<<dim3(16, 32), 256, gemm_smem(128)>>>(
        m1, w2, fc2_b, nullptr, m2, NSEQ, HDIM, HDIM);
    // 8. fc3 + bias + residual -> fp32 out
    mma_gemm<64, false, true, false><<<dim3(4, 64), 256, gemm_smem(64)>>>(
        m2, w3, fc3_b, x1, out, NSEQ, EDIM, HDIM);
}